// round 7
// baseline (speedup 1.0000x reference)
#include <cuda_runtime.h>
#include <cuda_bf16.h>
#include <cstdint>

#define BATCH 512
#define TLEN  512
#define IDIM  128
#define HDIM  512
#define NCTA  128
#define NTHR  512

#define OFF_BSUM  0
#define OFF_XCH   1024                    // 8 pairs * 16 rows * 72 f32 * 4B = 36864
#define OFF_WH    38912
#define OFF_WL    (OFF_WH + 81920)
#define SMEM_BYTES (OFF_WL + 81920)       // 202752

// x and h in pre-split bf16 hi/lo form (packed pairs, low half = even col)
__device__ uint32_t g_xhi[BATCH * TLEN * IDIM / 2];
__device__ uint32_t g_xlo[BATCH * TLEN * IDIM / 2];
__device__ uint32_t g_hhi[2][BATCH * HDIM / 2];
__device__ uint32_t g_hlo[2][BATCH * HDIM / 2];
__device__ unsigned g_count, g_gen;

__device__ __forceinline__ uint32_t smem_u32(const void* p) {
    uint32_t a;
    asm("{ .reg .u64 t; cvta.to.shared.u64 t, %1; cvt.u32.u64 %0, t; }" : "=r"(a) : "l"(p));
    return a;
}
#define SWZ(o) ((o) ^ (((o) >> 3) & 0x70))

__device__ __forceinline__ void ldm4(uint32_t* r, uint32_t addr) {
    asm volatile("ldmatrix.sync.aligned.m8n8.x4.shared.b16 {%0,%1,%2,%3}, [%4];"
        : "=r"(r[0]), "=r"(r[1]), "=r"(r[2]), "=r"(r[3]) : "r"(addr));
}
__device__ __forceinline__ void mma16816(float* d, const uint32_t* a, const uint32_t* b) {
    asm volatile("mma.sync.aligned.m16n8k16.row.col.f32.bf16.bf16.f32 "
        "{%0,%1,%2,%3},{%4,%5,%6,%7},{%8,%9},{%0,%1,%2,%3};"
        : "+f"(d[0]), "+f"(d[1]), "+f"(d[2]), "+f"(d[3])
        : "r"(a[0]), "r"(a[1]), "r"(a[2]), "r"(a[3]), "r"(b[0]), "r"(b[1]));
}
__device__ __forceinline__ uint32_t ldcg_u32(const uint32_t* p) {
    uint32_t v;
    asm volatile("ld.global.cg.b32 %0, [%1];" : "=r"(v) : "l"(p));
    return v;
}

// ---- monotonic grid barrier ----
__device__ __forceinline__ void gb_arrive(int tid) {
    if (tid == 0) {
        __threadfence();
        unsigned my = *(volatile unsigned*)&g_gen;
        if (atomicAdd(&g_count, 1u) == NCTA - 1) {
            g_count = 0;
            __threadfence();
            *(volatile unsigned*)&g_gen = my + 1;
        }
    }
}
__device__ __forceinline__ void gb_wait(int tid, unsigned target) {
    if (tid == 0) {
        while ((int)(*(volatile unsigned*)&g_gen - target) < 0) { }
        __threadfence();
    }
    __syncthreads();
}

// hi/lo bf16 split of a float4 -> two packed uint32 pairs each
__device__ __forceinline__ void split4(float4 v, uint32_t* hi, uint32_t* lo) {
    __nv_bfloat162 h0 = __floats2bfloat162_rn(v.x, v.y);
    __nv_bfloat162 h1 = __floats2bfloat162_rn(v.z, v.w);
    __nv_bfloat162 l0 = __floats2bfloat162_rn(v.x - __bfloat162float(h0.x),
                                              v.y - __bfloat162float(h0.y));
    __nv_bfloat162 l1 = __floats2bfloat162_rn(v.z - __bfloat162float(h1.x),
                                              v.w - __bfloat162float(h1.y));
    hi[0] = *(uint32_t*)&h0; hi[1] = *(uint32_t*)&h1;
    lo[0] = *(uint32_t*)&l0; lo[1] = *(uint32_t*)&l1;
}
// weights: split and store into hi/lo SMEM
__device__ __forceinline__ void cvt_sts(float4 v, uint32_t ah, uint32_t al) {
    uint32_t hw[2], lw[2];
    split4(v, hw, lw);
    uint64_t hv = ((uint64_t)hw[1] << 32) | hw[0];
    uint64_t lv = ((uint64_t)lw[1] << 32) | lw[0];
    asm volatile("st.shared.b64 [%0], %1;" :: "r"(ah), "l"(hv) : "memory");
    asm volatile("st.shared.b64 [%0], %1;" :: "r"(al), "l"(lv) : "memory");
}

__device__ __forceinline__ float sig_(float x) { return 1.0f / (1.0f + __expf(-x)); }
__device__ __forceinline__ float tnh_(float x) { return 2.0f / (1.0f + __expf(-2.0f * x)) - 1.0f; }

__global__ void __launch_bounds__(NTHR, 1) lstm_mma3(
    const float* __restrict__ x,
    const float* __restrict__ eWih, const float* __restrict__ eWhh,
    const float* __restrict__ ebih, const float* __restrict__ ebhh,
    const float* __restrict__ dWih, const float* __restrict__ dWhh,
    const float* __restrict__ dbih, const float* __restrict__ dbhh,
    const float* __restrict__ fcW,  const float* __restrict__ fcb,
    float* __restrict__ out)
{
    extern __shared__ __align__(1024) char smem[];
    const uint32_t sb = smem_u32(smem);
    const int tid = threadIdx.x, wid = tid >> 5, lane = tid & 31;
    const int p  = wid >> 1;            // pair 0..7 -> rows 16p..16p+15
    const int kp = wid & 1;             // split-K parity
    const int jb = blockIdx.x * 16;     // h-col base (32 slices)
    const int b0 = blockIdx.y * 128;    // batch base (4 groups)
    const int lq = lane >> 2;           // 0..7
    const int lr = (lane & 3) << 1;     // 0,2,4,6
    const int cid = blockIdx.y * 32 + blockIdx.x;

    float* bsum = (float*)(smem + OFF_BSUM);
    char*  xch  = smem + OFF_XCH + p * 4608;   // 16 rows x 72 f32

    unsigned gbase = 0;
    if (tid == 0) gbase = *(volatile unsigned*)&g_gen;

    // ---- prologue: zero h0 slice + convert x to bf16 hi/lo (whole grid) ----
    for (int i = tid; i < 1024; i += NTHR) {
        int r = i >> 3, cp = i & 7;
        g_hhi[0][(b0 + r) * 256 + jb / 2 + cp] = 0u;
        g_hlo[0][(b0 + r) * 256 + jb / 2 + cp] = 0u;
    }
    for (size_t j = (size_t)cid * NTHR + tid; j < (size_t)BATCH * TLEN * IDIM / 4;
         j += (size_t)NCTA * NTHR) {
        float4 v = *(const float4*)(x + 4 * j);
        uint32_t hw[2], lw[2];
        split4(v, hw, lw);
        *(uint2*)&g_xhi[2 * j] = make_uint2(hw[0], hw[1]);
        *(uint2*)&g_xlo[2 * j] = make_uint2(lw[0], lw[1]);
    }

    float cst[8];
    #pragma unroll
    for (int j = 0; j < 8; ++j) cst[j] = 0.0f;

    gb_arrive(tid);
    gb_wait(tid, gbase + 1);

    uint32_t bufA[16], bufB[16];   // [ki*8 + q] hi, [ki*8 + 4 + q] lo

    #pragma unroll 1
    for (int s = 0; s < 2 * TLEN; ++s) {
        const int dec = (s >= TLEN) ? 1 : 0;
        const int t = dec ? s - TLEN : s;
        const uint32_t* hhi = g_hhi[s & 1];
        const uint32_t* hlo = g_hlo[s & 1];

        // ---- per-phase weight + bias preload (hi/lo bf16 in SMEM) ----
        if (s == 0 || s == TLEN) {
            const float* Wih = dec ? dWih : eWih;
            const float* Whh = dec ? dWhh : eWhh;
            const float* bi  = dec ? dbih : ebih;
            const float* bh  = dec ? dbhh : ebhh;
            #pragma unroll 1
            for (int i = tid; i < 10240; i += NTHR) {   // 64 rows x 160 float4
                int rl = i / 160, k4 = i % 160;
                int c = k4 >> 4, kin = k4 & 15;
                int grow = (rl >> 4) * HDIM + jb + (rl & 15);
                const float* sp = (c < 2) ? (Wih + (size_t)grow * IDIM + c * 64 + kin * 4)
                                          : (Whh + (size_t)grow * HDIM + (c - 2) * 64 + kin * 4);
                float4 v = *(const float4*)sp;
                uint32_t off = (uint32_t)c * 8192u + SWZ((uint32_t)rl * 128u + (uint32_t)kin * 8u);
                cvt_sts(v, sb + OFF_WH + off, sb + OFF_WL + off);
            }
            if (tid < 64) {
                int g = tid >> 4, j = tid & 15;
                bsum[tid] = bi[g * HDIM + jb + j] + bh[g * HDIM + jb + j];
            }
            __syncthreads();
        }

        float acc[8][4];
        #pragma unroll
        for (int nt = 0; nt < 8; ++nt)
            #pragma unroll
            for (int q = 0; q < 4; ++q) acc[nt][q] = 0.0f;

        // prefetch A fragments of chunk c (pre-split bf16 hi/lo, direct LDG.32)
        auto pf = [&](int c, uint32_t* buf) {
            #pragma unroll
            for (int ki = 0; ki < 2; ++ki) {
                const int ks = kp + 2 * ki;
                #pragma unroll
                for (int q = 0; q < 4; ++q) {
                    int r  = 16 * p + lq + (q & 1) * 8;
                    int kk = ks * 16 + lr + (q >> 1) * 8;
                    if (c < 2) {
                        size_t w = ((size_t)(b0 + r) * TLEN + t) * 64 + (size_t)(c * 64 + kk) / 2;
                        buf[ki * 8 + q]     = ldcg_u32(g_xhi + w);
                        buf[ki * 8 + 4 + q] = ldcg_u32(g_xlo + w);
                    } else {
                        size_t w = (size_t)(b0 + r) * 256 + (size_t)((c - 2) * 64 + kk) / 2;
                        buf[ki * 8 + q]     = ldcg_u32(hhi + w);
                        buf[ki * 8 + 4 + q] = ldcg_u32(hlo + w);
                    }
                }
            }
        };

        auto compute = [&](int c, const uint32_t* buf) {
            const uint32_t wb = sb + OFF_WH + (uint32_t)c * 8192u;
            #pragma unroll
            for (int ki = 0; ki < 2; ++ki) {
                const int ks = kp + 2 * ki;
                uint32_t bh[16], bl[16];
                #pragma unroll
                for (int pp = 0; pp < 4; ++pp) {
                    uint32_t brow = (uint32_t)(pp * 16 + ((lane & 16) ? 8 : 0) + (lane & 7));
                    uint32_t boff = SWZ(brow * 128u + (uint32_t)ks * 32u + ((lane & 8) ? 16u : 0u));
                    ldm4(bh + 4 * pp, wb + boff);
                    ldm4(bl + 4 * pp, wb + 81920u + boff);
                }
                const uint32_t* ah = buf + ki * 8;
                const uint32_t* al = buf + ki * 8 + 4;
                #pragma unroll
                for (int nt = 0; nt < 8; ++nt) {
                    mma16816(acc[nt], ah, bh + 2 * nt);
                    mma16816(acc[nt], al, bh + 2 * nt);
                    mma16816(acc[nt], ah, bl + 2 * nt);
                }
            }
        };

        // x-chunks (h-independent) run before the barrier wait
        pf(0, bufA); pf(1, bufB);
        compute(0, bufA);
        compute(1, bufB);
        gb_wait(tid, gbase + 1 + (unsigned)s);
        pf(2, bufA);
        #pragma unroll 1
        for (int c = 2; c < 10; ++c) {
            uint32_t* cur = (c & 1) ? bufB : bufA;
            uint32_t* nxt = (c & 1) ? bufA : bufB;
            if (c < 9) pf(c + 1, nxt);
            compute(c, cur);
        }

        // ---- split-K exchange + fused gate epilogue ----
        if (kp) {
            #pragma unroll
            for (int nt = 0; nt < 8; ++nt)
                #pragma unroll
                for (int qr = 0; qr < 2; ++qr) {
                    uint32_t rowl = (uint32_t)(lq + qr * 8);
                    uint32_t col  = (uint32_t)(nt * 8 + lr);
                    *(float2*)(xch + rowl * 288 + col * 4) =
                        make_float2(acc[nt][2 * qr], acc[nt][2 * qr + 1]);
                }
        }
        __syncthreads();
        if (!kp) {
            #pragma unroll
            for (int nt = 0; nt < 8; ++nt)
                #pragma unroll
                for (int qr = 0; qr < 2; ++qr) {
                    uint32_t rowl = (uint32_t)(lq + qr * 8);
                    uint32_t col  = (uint32_t)(nt * 8 + lr);
                    float2 pv = *(const float2*)(xch + rowl * 288 + col * 4);
                    acc[nt][2 * qr]     += pv.x;
                    acc[nt][2 * qr + 1] += pv.y;
                }
            const int nb = (s + 1) & 1;
            #pragma unroll
            for (int qr = 0; qr < 2; ++qr) {
                const int r = 16 * p + lq + qr * 8;
                #pragma unroll
                for (int nh = 0; nh < 2; ++nh) {
                    float hv[2];
                    #pragma unroll
                    for (int e = 0; e < 2; ++e) {
                        const int q = 2 * qr + e;
                        const int j = nh * 8 + lr + e;
                        float pi  = acc[nh][q]     + bsum[j];
                        float pf_ = acc[2 + nh][q] + bsum[16 + j];
                        float pg  = acc[4 + nh][q] + bsum[32 + j];
                        float po  = acc[6 + nh][q] + bsum[48 + j];
                        float iv = sig_(pi), fv = sig_(pf_), gv = tnh_(pg), ov = sig_(po);
                        const int ci = qr * 4 + nh * 2 + e;
                        float cn = fv * cst[ci] + iv * gv;
                        cst[ci] = cn;
                        hv[e] = ov * tnh_(cn);
                    }
                    // store h as packed bf16 hi/lo pair
                    __nv_bfloat162 h2 = __floats2bfloat162_rn(hv[0], hv[1]);
                    __nv_bfloat162 l2 = __floats2bfloat162_rn(hv[0] - __bfloat162float(h2.x),
                                                              hv[1] - __bfloat162float(h2.y));
                    const size_t w = (size_t)(b0 + r) * 256 + jb / 2 + nh * 4 + (lr >> 1);
                    g_hhi[nb][w] = *(uint32_t*)&h2;
                    g_hlo[nb][w] = *(uint32_t*)&l2;
                }
            }
            __threadfence();
        }
        __syncthreads();
        gb_arrive(tid);
    }

    // ---- fc epilogue: final h is in buffer 0 ----
    gb_wait(tid, gbase + 1 + 2 * TLEN);
    if (blockIdx.x == 0) {
        for (int r = wid; r < 128; r += 16) {
            const size_t base = (size_t)(b0 + r) * 256;
            float ssum = 0.0f;
            #pragma unroll 4
            for (int kk = lane; kk < 256; kk += 32) {
                uint32_t hw = ldcg_u32(&g_hhi[0][base + kk]);
                uint32_t lw = ldcg_u32(&g_hlo[0][base + kk]);
                __nv_bfloat162 h2 = *(__nv_bfloat162*)&hw;
                __nv_bfloat162 l2 = *(__nv_bfloat162*)&lw;
                float v0 = __bfloat162float(h2.x) + __bfloat162float(l2.x);
                float v1 = __bfloat162float(h2.y) + __bfloat162float(l2.y);
                ssum += v0 * fcW[2 * kk] + v1 * fcW[2 * kk + 1];
            }
            #pragma unroll
            for (int o = 16; o; o >>= 1) ssum += __shfl_xor_sync(0xffffffffu, ssum, o);
            if (lane == 0) out[b0 + r] = ssum + fcb[0];
        }
    }
}

extern "C" void kernel_launch(void* const* d_in, const int* in_sizes, int n_in,
                              void* d_out, int out_size)
{
    (void)in_sizes; (void)n_in; (void)out_size;
    cudaFuncSetAttribute(lstm_mma3, cudaFuncAttributeMaxDynamicSharedMemorySize, SMEM_BYTES);
    dim3 grid(32, 4);   // 32 h-slices x 4 batch groups = 128 CTAs (1/SM)
    lstm_mma3<<<grid, NTHR, SMEM_BYTES>>>(
        (const float*)d_in[0],
        (const float*)d_in[1], (const float*)d_in[2],
        (const float*)d_in[3], (const float*)d_in[4],
        (const float*)d_in[5], (const float*)d_in[6],
        (const float*)d_in[7], (const float*)d_in[8],
        (const float*)d_in[9], (const float*)d_in[10],
        (float*)d_out);
}

// round 8
// speedup vs baseline: 1.0326x; 1.0326x over previous
#include <cuda_runtime.h>
#include <cuda_bf16.h>
#include <cstdint>

#define BATCH 512
#define TLEN  512
#define IDIM  128
#define HDIM  512
#define NCTA  128
#define NTHR  512

#define OFF_BSUM  0
#define OFF_CST   1024                    // 128 rows * 18 f32 = 9216 B
#define OFF_XCH   10240                   // 4 slots * 8704 B = 34816
#define OFF_WH    45056                   // 81920 (1024-aligned)
#define OFF_WL    (OFF_WH + 81920)
#define SMEM_BYTES (OFF_WL + 81920)       // 208896

// x and h in pre-split bf16 hi/lo, fragment-permuted word layout:
// per 8-word group, k-pair d (0..7) stored at slot 2*(d&3) + (d>>2)
__device__ uint32_t g_xhi[BATCH * TLEN * IDIM / 2];
__device__ uint32_t g_xlo[BATCH * TLEN * IDIM / 2];
__device__ uint32_t g_hhi[2][BATCH * HDIM / 2];
__device__ uint32_t g_hlo[2][BATCH * HDIM / 2];
__device__ unsigned g_count, g_gen;

__device__ __forceinline__ uint32_t smem_u32(const void* p) {
    uint32_t a;
    asm("{ .reg .u64 t; cvta.to.shared.u64 t, %1; cvt.u32.u64 %0, t; }" : "=r"(a) : "l"(p));
    return a;
}
#define SWZ(o) ((o) ^ (((o) >> 3) & 0x70))

__device__ __forceinline__ void ldm4(uint32_t* r, uint32_t addr) {
    asm volatile("ldmatrix.sync.aligned.m8n8.x4.shared.b16 {%0,%1,%2,%3}, [%4];"
        : "=r"(r[0]), "=r"(r[1]), "=r"(r[2]), "=r"(r[3]) : "r"(addr));
}
__device__ __forceinline__ void mma16816(float* d, const uint32_t* a, const uint32_t* b) {
    asm volatile("mma.sync.aligned.m16n8k16.row.col.f32.bf16.bf16.f32 "
        "{%0,%1,%2,%3},{%4,%5,%6,%7},{%8,%9},{%0,%1,%2,%3};"
        : "+f"(d[0]), "+f"(d[1]), "+f"(d[2]), "+f"(d[3])
        : "r"(a[0]), "r"(a[1]), "r"(a[2]), "r"(a[3]), "r"(b[0]), "r"(b[1]));
}
__device__ __forceinline__ uint32_t ldcg_u32(const uint32_t* p) {
    uint32_t v;
    asm volatile("ld.global.cg.b32 %0, [%1];" : "=r"(v) : "l"(p));
    return v;
}
__device__ __forceinline__ uint2 ldcg_u2(const uint32_t* p) {
    uint2 v;
    asm volatile("ld.global.cg.v2.b32 {%0,%1}, [%2];" : "=r"(v.x), "=r"(v.y) : "l"(p));
    return v;
}

// ---- monotonic grid barrier ----
__device__ __forceinline__ void gb_arrive(int tid) {
    if (tid == 0) {
        __threadfence();
        unsigned my = *(volatile unsigned*)&g_gen;
        if (atomicAdd(&g_count, 1u) == NCTA - 1) {
            g_count = 0;
            __threadfence();
            *(volatile unsigned*)&g_gen = my + 1;
        }
    }
}
__device__ __forceinline__ void gb_wait(int tid, unsigned target) {
    if (tid == 0) {
        while ((int)(*(volatile unsigned*)&g_gen - target) < 0) { }
        __threadfence();
    }
    __syncthreads();
}

__device__ __forceinline__ void split4(float4 v, uint32_t* hi, uint32_t* lo) {
    __nv_bfloat162 h0 = __floats2bfloat162_rn(v.x, v.y);
    __nv_bfloat162 h1 = __floats2bfloat162_rn(v.z, v.w);
    __nv_bfloat162 l0 = __floats2bfloat162_rn(v.x - __bfloat162float(h0.x),
                                              v.y - __bfloat162float(h0.y));
    __nv_bfloat162 l1 = __floats2bfloat162_rn(v.z - __bfloat162float(h1.x),
                                              v.w - __bfloat162float(h1.y));
    hi[0] = *(uint32_t*)&h0; hi[1] = *(uint32_t*)&h1;
    lo[0] = *(uint32_t*)&l0; lo[1] = *(uint32_t*)&l1;
}
__device__ __forceinline__ void cvt_sts(float4 v, uint32_t ah, uint32_t al) {
    uint32_t hw[2], lw[2];
    split4(v, hw, lw);
    uint64_t hv = ((uint64_t)hw[1] << 32) | hw[0];
    uint64_t lv = ((uint64_t)lw[1] << 32) | lw[0];
    asm volatile("st.shared.b64 [%0], %1;" :: "r"(ah), "l"(hv) : "memory");
    asm volatile("st.shared.b64 [%0], %1;" :: "r"(al), "l"(lv) : "memory");
}

__device__ __forceinline__ float sig_(float x) { return 1.0f / (1.0f + __expf(-x)); }
__device__ __forceinline__ float tnh_(float x) { return 2.0f / (1.0f + __expf(-2.0f * x)) - 1.0f; }

__global__ void __launch_bounds__(NTHR, 1) lstm_mma4(
    const float* __restrict__ x,
    const float* __restrict__ eWih, const float* __restrict__ eWhh,
    const float* __restrict__ ebih, const float* __restrict__ ebhh,
    const float* __restrict__ dWih, const float* __restrict__ dWhh,
    const float* __restrict__ dbih, const float* __restrict__ dbhh,
    const float* __restrict__ fcW,  const float* __restrict__ fcb,
    float* __restrict__ out)
{
    extern __shared__ __align__(1024) char smem[];
    const uint32_t sb = smem_u32(smem);
    const int tid = threadIdx.x, wid = tid >> 5, lane = tid & 31;
    const int m  = wid & 3;             // m-tile: rows 32m..32m+31
    const int kp = wid >> 2;            // split-K 4-way: ks = kp
    const int bx = blockIdx.x;          // 32 h-slices
    const int jb = bx * 16;
    const int b0 = blockIdx.y * 128;    // batch base (4 groups)
    const int lq = lane >> 2;           // 0..7
    const int lr = (lane & 3) << 1;     // 0,2,4,6
    const int cid = blockIdx.y * 32 + bx;

    float* bsum = (float*)(smem + OFF_BSUM);

    unsigned gbase = 0;
    if (tid == 0) gbase = *(volatile unsigned*)&g_gen;

    // ---- prologue: zero h0 + cst, convert x to permuted bf16 hi/lo ----
    for (int i = tid; i < 1024; i += NTHR) {
        int r = i >> 3, ws = i & 7;
        size_t wi = (size_t)(b0 + r) * 256 + (size_t)bx * 8 + ws;
        g_hhi[0][wi] = 0u; g_hlo[0][wi] = 0u;
    }
    for (int i = tid; i < 2304; i += NTHR) ((float*)(smem + OFF_CST))[i] = 0.0f;
    for (size_t j = (size_t)cid * NTHR + tid; j < (size_t)BATCH * TLEN * IDIM / 4;
         j += (size_t)NCTA * NTHR) {
        float4 v = *(const float4*)(x + 4 * j);
        uint32_t hw[2], lw[2];
        split4(v, hw, lw);
        #pragma unroll
        for (int k = 0; k < 2; ++k) {
            size_t P = 2 * j + k;
            uint32_t w = (uint32_t)(P & 63);
            uint32_t d = w & 7;
            uint32_t slot = 2u * (d & 3) + (d >> 2);
            size_t widx = (P & ~(size_t)63) + (w & 32) + (((w >> 3) & 3) << 3) + slot;
            g_xhi[widx] = hw[k];
            g_xlo[widx] = lw[k];
        }
    }

    gb_arrive(tid);
    gb_wait(tid, gbase + 1);

    uint32_t bufA[8], bufB[8];

    #pragma unroll 1
    for (int s = 0; s < 2 * TLEN; ++s) {
        const int dec = (s >= TLEN) ? 1 : 0;
        const int t = dec ? s - TLEN : s;
        const uint32_t* hhi = g_hhi[s & 1];
        const uint32_t* hlo = g_hlo[s & 1];

        // ---- per-phase weight + bias preload (hi/lo bf16, SW128) ----
        if (s == 0 || s == TLEN) {
            const float* Wih = dec ? dWih : eWih;
            const float* Whh = dec ? dWhh : eWhh;
            const float* bi  = dec ? dbih : ebih;
            const float* bh_ = dec ? dbhh : ebhh;
            #pragma unroll 1
            for (int i = tid; i < 10240; i += NTHR) {   // 64 rows x 160 float4
                int rl = i / 160, k4 = i % 160;
                int c = k4 >> 4, kin = k4 & 15;
                int grow = (rl >> 4) * HDIM + jb + (rl & 15);
                const float* sp = (c < 2) ? (Wih + (size_t)grow * IDIM + c * 64 + kin * 4)
                                          : (Whh + (size_t)grow * HDIM + (c - 2) * 64 + kin * 4);
                float4 v = *(const float4*)sp;
                uint32_t off = (uint32_t)c * 8192u + SWZ((uint32_t)rl * 128u + (uint32_t)kin * 8u);
                cvt_sts(v, sb + OFF_WH + off, sb + OFF_WL + off);
            }
            if (tid < 64) {
                int g = tid >> 4, j = tid & 15;
                bsum[tid] = bi[g * HDIM + jb + j] + bh_[g * HDIM + jb + j];
            }
            __syncthreads();
        }

        float acc[2][8][4];
        #pragma unroll
        for (int fi = 0; fi < 2; ++fi)
            #pragma unroll
            for (int nt = 0; nt < 8; ++nt)
                #pragma unroll
                for (int q = 0; q < 4; ++q) acc[fi][nt][q] = 0.0f;

        auto pf_hi = [&](int c, uint32_t* buf) {
            #pragma unroll
            for (int fi = 0; fi < 2; ++fi)
                #pragma unroll
                for (int rq = 0; rq < 2; ++rq) {
                    const int r = b0 + 32 * m + fi * 16 + lq + 8 * rq;
                    uint2 v;
                    if (c < 2)
                        v = ldcg_u2(g_xhi + ((size_t)r * TLEN + t) * 64
                                          + (size_t)(c * 32 + kp * 8 + lr));
                    else
                        v = ldcg_u2(hhi + (size_t)r * 256
                                        + (size_t)((c - 2) * 32 + kp * 8 + lr));
                    buf[fi * 4 + rq]     = v.x;
                    buf[fi * 4 + 2 + rq] = v.y;
                }
        };
        auto pf_lo = [&](int c, uint32_t* buf) {
            #pragma unroll
            for (int fi = 0; fi < 2; ++fi)
                #pragma unroll
                for (int rq = 0; rq < 2; ++rq) {
                    const int r = b0 + 32 * m + fi * 16 + lq + 8 * rq;
                    uint2 v;
                    if (c < 2)
                        v = ldcg_u2(g_xlo + ((size_t)r * TLEN + t) * 64
                                          + (size_t)(c * 32 + kp * 8 + lr));
                    else
                        v = ldcg_u2(hlo + (size_t)r * 256
                                        + (size_t)((c - 2) * 32 + kp * 8 + lr));
                    buf[fi * 4 + rq]     = v.x;
                    buf[fi * 4 + 2 + rq] = v.y;
                }
        };
        auto body = [&](int c, const uint32_t* hib, const uint32_t* lob) {
            const uint32_t wb = sb + OFF_WH + (uint32_t)c * 8192u;
            const uint32_t rbs = (uint32_t)(((lane & 16) ? 8 : 0) + (lane & 7));
            const uint32_t kc  = (uint32_t)(kp * 32 + ((lane & 8) ? 16 : 0));
            #pragma unroll
            for (int pp = 0; pp < 4; ++pp) {
                uint32_t bhf[4], blf[4];
                uint32_t boff = SWZ(((uint32_t)(pp * 16) + rbs) * 128u + kc);
                ldm4(bhf, wb + boff);
                ldm4(blf, wb + 81920u + boff);
                #pragma unroll
                for (int fi = 0; fi < 2; ++fi)
                    #pragma unroll
                    for (int ntl = 0; ntl < 2; ++ntl)
                        mma16816(acc[fi][pp * 2 + ntl], hib + fi * 4, bhf + 2 * ntl);
                #pragma unroll
                for (int fi = 0; fi < 2; ++fi)
                    #pragma unroll
                    for (int ntl = 0; ntl < 2; ++ntl)
                        mma16816(acc[fi][pp * 2 + ntl], hib + fi * 4, blf + 2 * ntl);
                #pragma unroll
                for (int fi = 0; fi < 2; ++fi)
                    #pragma unroll
                    for (int ntl = 0; ntl < 2; ++ntl)
                        mma16816(acc[fi][pp * 2 + ntl], lob + fi * 4, bhf + 2 * ntl);
            }
        };

        // x-chunks (h-independent) before the barrier wait
        pf_hi(0, bufA); pf_hi(1, bufB);
        { uint32_t lob[8]; pf_lo(0, lob); body(0, bufA, lob); }
        { uint32_t lob[8]; pf_lo(1, lob); body(1, bufB, lob); }
        gb_wait(tid, gbase + 1 + (unsigned)s);
        pf_hi(2, bufA);
        #pragma unroll 1
        for (int c = 2; c < 10; ++c) {
            uint32_t* cur = (c & 1) ? bufB : bufA;
            uint32_t* nxt = (c & 1) ? bufA : bufB;
            uint32_t lob[8];
            pf_lo(c, lob);
            if (c < 9) pf_hi(c + 1, nxt);
            body(c, cur, lob);
        }

        // ---- split-K reduce (3 rounds) ----
        const uint32_t xslot = sb + OFF_XCH + (uint32_t)m * 8704u;
        #pragma unroll 1
        for (int rr = 1; rr <= 3; ++rr) {
            if (kp == rr) {
                #pragma unroll
                for (int fi = 0; fi < 2; ++fi)
                    #pragma unroll
                    for (int nt = 0; nt < 8; ++nt)
                        #pragma unroll
                        for (int qr = 0; qr < 2; ++qr) {
                            uint32_t a = xslot + (uint32_t)(fi * 16 + lq + 8 * qr) * 272u
                                               + (uint32_t)(nt * 8 + lr) * 4u;
                            asm volatile("st.shared.v2.f32 [%0], {%1,%2};" :: "r"(a),
                                "f"(acc[fi][nt][2 * qr]), "f"(acc[fi][nt][2 * qr + 1]) : "memory");
                        }
            }
            __syncthreads();
            if (kp == 0) {
                #pragma unroll
                for (int fi = 0; fi < 2; ++fi)
                    #pragma unroll
                    for (int nt = 0; nt < 8; ++nt)
                        #pragma unroll
                        for (int qr = 0; qr < 2; ++qr) {
                            uint32_t a = xslot + (uint32_t)(fi * 16 + lq + 8 * qr) * 272u
                                               + (uint32_t)(nt * 8 + lr) * 4u;
                            float px, py;
                            asm volatile("ld.shared.v2.f32 {%0,%1}, [%2];"
                                : "=f"(px), "=f"(py) : "r"(a));
                            acc[fi][nt][2 * qr]     += px;
                            acc[fi][nt][2 * qr + 1] += py;
                        }
            }
            __syncthreads();
        }

        // ---- fused gate epilogue (kp==0 warps, all 4 gates in-warp) ----
        if (kp == 0) {
            float* cstp = (float*)(smem + OFF_CST);
            const int nb = (s + 1) & 1;
            #pragma unroll
            for (int fi = 0; fi < 2; ++fi)
                #pragma unroll
                for (int qr = 0; qr < 2; ++qr) {
                    const int rloc = 32 * m + fi * 16 + lq + 8 * qr;
                    float* cp = cstp + rloc * 18;
                    uint32_t hw[2], lw[2];
                    #pragma unroll
                    for (int nt = 0; nt < 2; ++nt) {
                        float hv[2];
                        #pragma unroll
                        for (int e = 0; e < 2; ++e) {
                            const int q = 2 * qr + e, j = nt * 8 + lr + e;
                            float pi  = acc[fi][nt][q]     + bsum[j];
                            float pf_ = acc[fi][nt + 2][q] + bsum[16 + j];
                            float pg  = acc[fi][nt + 4][q] + bsum[32 + j];
                            float po  = acc[fi][nt + 6][q] + bsum[48 + j];
                            float iv = sig_(pi), fv = sig_(pf_), gv = tnh_(pg), ov = sig_(po);
                            float cn = fv * cp[j] + iv * gv;
                            cp[j] = cn;
                            hv[e] = ov * tnh_(cn);
                        }
                        __nv_bfloat162 h2 = __floats2bfloat162_rn(hv[0], hv[1]);
                        __nv_bfloat162 l2 = __floats2bfloat162_rn(hv[0] - __bfloat162float(h2.x),
                                                                  hv[1] - __bfloat162float(h2.y));
                        hw[nt] = *(uint32_t*)&h2;
                        lw[nt] = *(uint32_t*)&l2;
                    }
                    const size_t wi = (size_t)(b0 + rloc) * 256 + (size_t)bx * 8 + lr;
                    *(uint2*)&g_hhi[nb][wi] = make_uint2(hw[0], hw[1]);
                    *(uint2*)&g_hlo[nb][wi] = make_uint2(lw[0], lw[1]);
                }
            __threadfence();
        }
        __syncthreads();
        gb_arrive(tid);
    }

    // ---- fc epilogue: final h in buffer 0 (permuted layout) ----
    gb_wait(tid, gbase + 1 + 2 * TLEN);
    if (bx == 0) {
        for (int r = wid; r < 128; r += 16) {
            const size_t base = (size_t)(b0 + r) * 256;
            float ssum = 0.0f;
            for (int kk = lane; kk < 256; kk += 32) {
                uint32_t hwv = ldcg_u32(&g_hhi[0][base + kk]);
                uint32_t lwv = ldcg_u32(&g_hlo[0][base + kk]);
                int slot = kk & 7;
                int d = (slot & 1) * 4 + (slot >> 1);
                int J = (kk >> 5) * 64 + (((kk >> 3) & 3) * 8 + d) * 2;
                __nv_bfloat162 h2 = *(__nv_bfloat162*)&hwv;
                __nv_bfloat162 l2 = *(__nv_bfloat162*)&lwv;
                ssum += (__bfloat162float(h2.x) + __bfloat162float(l2.x)) * fcW[J]
                      + (__bfloat162float(h2.y) + __bfloat162float(l2.y)) * fcW[J + 1];
            }
            #pragma unroll
            for (int o = 16; o; o >>= 1) ssum += __shfl_xor_sync(0xffffffffu, ssum, o);
            if (lane == 0) out[b0 + r] = ssum + fcb[0];
        }
    }
}

extern "C" void kernel_launch(void* const* d_in, const int* in_sizes, int n_in,
                              void* d_out, int out_size)
{
    (void)in_sizes; (void)n_in; (void)out_size;
    cudaFuncSetAttribute(lstm_mma4, cudaFuncAttributeMaxDynamicSharedMemorySize, SMEM_BYTES);
    dim3 grid(32, 4);   // 32 h-slices x 4 batch groups = 128 CTAs (1/SM)
    lstm_mma4<<<grid, NTHR, SMEM_BYTES>>>(
        (const float*)d_in[0],
        (const float*)d_in[1], (const float*)d_in[2],
        (const float*)d_in[3], (const float*)d_in[4],
        (const float*)d_in[5], (const float*)d_in[6],
        (const float*)d_in[7], (const float*)d_in[8],
        (const float*)d_in[9], (const float*)d_in[10],
        (float*)d_out);
}